// round 15
// baseline (speedup 1.0000x reference)
#include <cuda_runtime.h>

#define NB 64
#define NP 1024
#define CF 16
#define KK 16
#define BN_EPS 1e-5f

typedef unsigned long long u64;

#define FMA2(d, a, b, c) \
    asm("fma.rn.f32x2 %0, %1, %2, %3;" : "=l"(d) : "l"(a), "l"(b), "l"(c))
#define PACK2(d, x) \
    asm("mov.b64 %0, {%1, %1};" : "=l"(d) : "f"(x))
#define UNPACK2(lo, hi, v) \
    asm("mov.b64 {%0, %1}, %2;" : "=f"(lo), "=f"(hi) : "l"(v))

// act XOR swizzle: 8-granular, spreads phase-0 scatter across 4x banks.
#define SW(c) ((((c) >> 2) & 3) << 3)

// ---------------- static scratch (no allocations allowed) ----------------
__device__ float g_C [NB*NP*64];
__device__ float g_Y [NB*NP*64];
__device__ float g_SC[NB*NP*64];
__device__ int   g_idx[NB*NP*KK];
__device__ int   g_valid[NB];
__device__ float g_W1t[64*64];     // W1 (BN-scaled), TRANSPOSED [c][o]
__device__ float g_W2t[64*64];
__device__ float g_W0at[CF*64], g_W0bt[CF*64], g_Wst[CF*64];
__device__ float g_t0[64], g_t1[64], g_t2[64], g_ts[64];

// ---------------- fold BN into weights / biases ----------------
__global__ void fold_kernel(const float* __restrict__ W0, const float* __restrict__ W1,
    const float* __restrict__ W2, const float* __restrict__ Ws,
    const float* g0,const float* b0,const float* m0,const float* v0,
    const float* g1,const float* b1,const float* m1,const float* v1,
    const float* g2,const float* b2,const float* m2,const float* v2,
    const float* gs,const float* bs,const float* ms,const float* vs)
{
    int t = blockIdx.x*blockDim.x + threadIdx.x;
    if (t < 64){
        float s0 = g0[t]*rsqrtf(v0[t]+BN_EPS); g_t0[t]=b0[t]-m0[t]*s0;
        float s1 = g1[t]*rsqrtf(v1[t]+BN_EPS); g_t1[t]=b1[t]-m1[t]*s1;
        float s2 = g2[t]*rsqrtf(v2[t]+BN_EPS); g_t2[t]=b2[t]-m2[t]*s2;
        float ss = gs[t]*rsqrtf(vs[t]+BN_EPS); g_ts[t]=bs[t]-ms[t]*ss;
    }
    if (t < 1024){
        int o = t >> 4, c = t & 15;
        float s0 = g0[o]*rsqrtf(v0[o]+BN_EPS);
        float ss = gs[o]*rsqrtf(vs[o]+BN_EPS);
        float wa = W0[o*32 + c], wb = W0[o*32 + 16 + c];
        g_W0at[c*64 + o] = (wa + wb)*s0;
        g_W0bt[c*64 + o] = wb*s0;
        g_Wst [c*64 + o] = Ws[o*16 + c]*ss;
    }
    if (t < 4096){
        int oo = t >> 6, cc = t & 63;
        g_W1t[cc*64 + oo] = W1[t]*(g1[oo]*rsqrtf(v1[oo]+BN_EPS));
        g_W2t[cc*64 + oo] = W2[t]*(g2[oo]*rsqrtf(v2[oo]+BN_EPS));
    }
}

// ---------------- KNN + fused prep: warp-per-point bitonic ----------------
__global__ void __launch_bounds__(256)
knn_kernel(const float* __restrict__ feats,
           const unsigned char* __restrict__ mask)
{
    const int n    = blockIdx.x >> 7;
    const int bloc = blockIdx.x & 127;
    const int warp = threadIdx.x >> 5;
    const int lane = threadIdx.x & 31;
    const int p    = bloc*8 + warp;

    __shared__ float px[NP], py[NP], rr[NP];
    __shared__ unsigned int heads[8][512];
    __shared__ float sx[8][CF];
    __shared__ int scnt;

    if (threadIdx.x == 0) scnt = 0;
    int mcnt = 0;
    for (int i = threadIdx.x; i < NP; i += 256){
        float2 xy = __ldg((const float2*)&feats[(n*NP + i)*(2+CF)]);
        px[i] = xy.x; py[i] = xy.y; rr[i] = xy.x*xy.x + xy.y*xy.y;
        if (bloc == 0 && mask[n*NP + i]) mcnt++;
    }
    if (threadIdx.x < 128){
        int lp = threadIdx.x >> 4, c = threadIdx.x & 15;
        sx[lp][c] = feats[(n*NP + bloc*8 + lp)*(2+CF) + 2 + c];
    }
    __syncthreads();
    if (bloc == 0 && mcnt) atomicAdd(&scnt, mcnt);

    const float xp = px[p], yp = py[p], rp = rr[p];
    const float nx = -2.f*xp, ny = -2.f*yp;

    unsigned int key[32];
#pragma unroll
    for (int i = 0; i < 32; i++){
        int q = i*32 + lane;
        float d = fmaxf(fmaf(nx, px[q], fmaf(ny, py[q], rp + rr[q])), 0.f);
        unsigned int kb = (__float_as_uint(d) & 0xFFFFFC00u) | (unsigned int)q;
        key[i] = (q == p) ? 0xFFFFFFFFu : kb;
    }
#pragma unroll
    for (int kk = 2; kk <= 32; kk <<= 1){
#pragma unroll
        for (int j = kk >> 1; j > 0; j >>= 1){
#pragma unroll
            for (int i = 0; i < 32; i++){
                int l = i ^ j;
                if (l > i){
                    unsigned int a = key[i], b = key[l];
                    unsigned int lo = a < b ? a : b;
                    unsigned int hi = a < b ? b : a;
                    if ((i & kk) == 0){ key[i] = lo; key[l] = hi; }
                    else              { key[i] = hi; key[l] = lo; }
                }
            }
        }
    }
#pragma unroll
    for (int j = 0; j < 16; j++) heads[warp][j*32 + lane] = key[j];

    int ptr = 0;
    unsigned int sel = 0;
#pragma unroll 1
    for (int r = 0; r < KK; r++){
        unsigned int h = (ptr < 16) ? heads[warp][ptr*32 + lane] : 0xFFFFFFFFu;
        unsigned int w = h;
#pragma unroll
        for (int d = 16; d; d >>= 1){
            unsigned int o = __shfl_xor_sync(0xFFFFFFFFu, w, d);
            w = (o < w) ? o : w;
        }
        if (h == w) ptr++;
        if (lane == r) sel = w;
    }
    if (lane < KK) g_idx[(n*NP + p)*KK + lane] = (int)(sel & 1023u);

    // ---- fused prep: per-point projections C, Y, shortcut ----
#pragma unroll
    for (int s = 0; s < 2; s++){
        const int idx = threadIdx.x + s*256;
        const int lp  = idx >> 6;
        const int o   = idx & 63;
        float a = 0.f, yb = 0.f, sc = 0.f;
#pragma unroll
        for (int c = 0; c < CF; c++){
            float x = sx[lp][c];
            a  = fmaf(x, g_W0at[c*64 + o], a);
            yb = fmaf(x, g_W0bt[c*64 + o], yb);
            sc = fmaf(x, g_Wst [c*64 + o], sc);
        }
        const int pt = n*NP + bloc*8 + lp;
        g_C[(size_t)pt*64 + o] = a + g_t0[o];
        g_Y[(size_t)pt*64 + o] = yb;
        float scv = sc + g_ts[o];
        if (mask[pt]) scv = 0.f;
        g_SC[(size_t)pt*64 + o] = scv;
    }

    if (bloc == 0){
        __syncthreads();
        if (threadIdx.x == 0) g_valid[n] = NP - scnt;
    }
}

// ---------------- edge kernel v12: 256 threads, 8Mx4N tile, 3 blocks/SM ----------------
// Same block tile (128 edges x 64 ch), same SMEM traffic and FMA2 count as
// R14, but tile split across 2x threads: regs ~75/thread -> 3 blocks/SM =
// 24 warps (was 16), hiding LDS latency at the balanced LSU=FMA2 floor.
#define SM_ACT    0                    // 64*128 floats = 32768 B (part overlaps)
#define SM_W      32768                // 64*64 floats = 16384 B
#define SM_VALIDF 49152                // 128 floats
#define SM_VCNT   49664                // 8 floats
#define SM_TOTAL  49696

__global__ void __launch_bounds__(256, 3)
edge_kernel(float* __restrict__ out)
{
    extern __shared__ char smraw[];
    float* act    = (float*)(smraw + SM_ACT);
    float* wsm    = (float*)(smraw + SM_W);
    float* part   = (float*)(smraw + SM_ACT);     // overlaps act (used after L2)
    float* validf = (float*)(smraw + SM_VALIDF);
    float* vcnt   = (float*)(smraw + SM_VCNT);

    const int tid  = threadIdx.x;
    const int lane = tid & 31;
    const int w    = tid >> 5;
    const int pt0  = blockIdx.x * 8;
    const int n    = pt0 >> 10;

    const int valid = g_valid[n];

    // ---- stage W1 (256 threads: 4 x float4 each) ----
    {
        const float4* src = (const float4*)g_W1t;
        float4* dst = (float4*)wsm;
#pragma unroll
        for (int i = 0; i < 4; i++) dst[tid + i*256] = __ldg(src + tid + i*256);
    }

    // ---- phase 0: coalesced Y/C gather, swizzled scatter into act ----
    // 8 warps x 16 edges each (half-warp per edge row).
    {
        const int half  = lane >> 4;
        const int chunk = lane & 15;
        const int sw    = (chunk & 3) << 3;   // == SW(chunk*4 + j), j<4
#pragma unroll 4
        for (int i = 0; i < 8; i++){
            const int e  = w*16 + i*2 + half;
            const int pt = pt0 + (e >> 4);
            const int q  = __ldg(&g_idx[pt*KK + (e & 15)]);
            if (chunk == 0) validf[e] = (q < valid) ? 1.f : 0.f;
            float4 y  = __ldg((const float4*)(g_Y + ((size_t)n*NP + q)*64) + chunk);
            float4 c4 = __ldg((const float4*)(g_C + (size_t)pt*64) + chunk);
            const int cc = chunk*4;
            const int es = e ^ sw;
            act[(cc+0)*128 + es] = fmaxf(c4.x - y.x, 0.f);
            act[(cc+1)*128 + es] = fmaxf(c4.y - y.y, 0.f);
            act[(cc+2)*128 + es] = fmaxf(c4.z - y.z, 0.f);
            act[(cc+3)*128 + es] = fmaxf(c4.w - y.w, 0.f);
        }
    }
    __syncthreads();

    if (tid < 8){
        float s = 0.f;
#pragma unroll
        for (int j = 0; j < 16; j++) s += validf[tid*16 + j];
        vcnt[tid] = s;
    }

    // ---- tiling: 16 M-tiles x 16 N-tiles; thread = 8M x 4N ----
    const int mt = tid & 15;
    const int nt = tid >> 4;
    const int m0 = mt * 8;
    const int o0 = nt * 4;

    u64 acc[16];   // acc[mi*2 + oj] = packed (o0+2oj, o0+2oj+1) for row m0+mi

    // ===== layer 1 =====
    {
        const u64* tp = (const u64*)(g_t1 + o0);
        u64 t0p = tp[0], t1p = tp[1];
#pragma unroll
        for (int mi = 0; mi < 8; mi++){ acc[mi*2+0]=t0p; acc[mi*2+1]=t1p; }
        const float* W = wsm + o0;
#pragma unroll 4
        for (int c = 0; c < 64; c++){
            const float* A = act + c*128 + (m0 ^ SW(c));
            float4 a0 = *(const float4*)(A);
            float4 a1 = *(const float4*)(A + 4);
            ulonglong2 b01 = *(const ulonglong2*)(W + c*64);
            u64 d0,d1,d2,d3,d4,d5,d6,d7;
            PACK2(d0, a0.x); PACK2(d1, a0.y); PACK2(d2, a0.z); PACK2(d3, a0.w);
            PACK2(d4, a1.x); PACK2(d5, a1.y); PACK2(d6, a1.z); PACK2(d7, a1.w);
            FMA2(acc[ 0], d0, b01.x, acc[ 0]); FMA2(acc[ 1], d0, b01.y, acc[ 1]);
            FMA2(acc[ 2], d1, b01.x, acc[ 2]); FMA2(acc[ 3], d1, b01.y, acc[ 3]);
            FMA2(acc[ 4], d2, b01.x, acc[ 4]); FMA2(acc[ 5], d2, b01.y, acc[ 5]);
            FMA2(acc[ 6], d3, b01.x, acc[ 6]); FMA2(acc[ 7], d3, b01.y, acc[ 7]);
            FMA2(acc[ 8], d4, b01.x, acc[ 8]); FMA2(acc[ 9], d4, b01.y, acc[ 9]);
            FMA2(acc[10], d5, b01.x, acc[10]); FMA2(acc[11], d5, b01.y, acc[11]);
            FMA2(acc[12], d6, b01.x, acc[12]); FMA2(acc[13], d6, b01.y, acc[13]);
            FMA2(acc[14], d7, b01.x, acc[14]); FMA2(acc[15], d7, b01.y, acc[15]);
        }
    }
    __syncthreads();   // all reads of act + wsm(W1) complete

    // relu + transposed writeback (swizzled); stage W2
#pragma unroll
    for (int oj = 0; oj < 2; oj++){
        float lo[8], hi[8];
#pragma unroll
        for (int mi = 0; mi < 8; mi++) UNPACK2(lo[mi], hi[mi], acc[mi*2 + oj]);
        float4 vl0 = { fmaxf(lo[0],0.f), fmaxf(lo[1],0.f), fmaxf(lo[2],0.f), fmaxf(lo[3],0.f) };
        float4 vl1 = { fmaxf(lo[4],0.f), fmaxf(lo[5],0.f), fmaxf(lo[6],0.f), fmaxf(lo[7],0.f) };
        float4 vh0 = { fmaxf(hi[0],0.f), fmaxf(hi[1],0.f), fmaxf(hi[2],0.f), fmaxf(hi[3],0.f) };
        float4 vh1 = { fmaxf(hi[4],0.f), fmaxf(hi[5],0.f), fmaxf(hi[6],0.f), fmaxf(hi[7],0.f) };
        const int olo = o0 + 2*oj;
        const int ms  = m0 ^ SW(olo);      // same SW for the whole 4-col group
        *(float4*)(act + (olo    )*128 + ms    ) = vl0;
        *(float4*)(act + (olo    )*128 + ms + 4) = vl1;
        *(float4*)(act + (olo + 1)*128 + ms    ) = vh0;
        *(float4*)(act + (olo + 1)*128 + ms + 4) = vh1;
    }
    {
        const float4* src = (const float4*)g_W2t;
        float4* dst = (float4*)wsm;
#pragma unroll
        for (int i = 0; i < 4; i++) dst[tid + i*256] = __ldg(src + tid + i*256);
    }
    __syncthreads();   // layer-1 activations + W2 ready

    // ===== layer 2 =====
    {
        const u64* tp = (const u64*)(g_t2 + o0);
        u64 t0p = tp[0], t1p = tp[1];
#pragma unroll
        for (int mi = 0; mi < 8; mi++){ acc[mi*2+0]=t0p; acc[mi*2+1]=t1p; }
        const float* W = wsm + o0;
#pragma unroll 4
        for (int c = 0; c < 64; c++){
            const float* A = act + c*128 + (m0 ^ SW(c));
            float4 a0 = *(const float4*)(A);
            float4 a1 = *(const float4*)(A + 4);
            ulonglong2 b01 = *(const ulonglong2*)(W + c*64);
            u64 d0,d1,d2,d3,d4,d5,d6,d7;
            PACK2(d0, a0.x); PACK2(d1, a0.y); PACK2(d2, a0.z); PACK2(d3, a0.w);
            PACK2(d4, a1.x); PACK2(d5, a1.y); PACK2(d6, a1.z); PACK2(d7, a1.w);
            FMA2(acc[ 0], d0, b01.x, acc[ 0]); FMA2(acc[ 1], d0, b01.y, acc[ 1]);
            FMA2(acc[ 2], d1, b01.x, acc[ 2]); FMA2(acc[ 3], d1, b01.y, acc[ 3]);
            FMA2(acc[ 4], d2, b01.x, acc[ 4]); FMA2(acc[ 5], d2, b01.y, acc[ 5]);
            FMA2(acc[ 6], d3, b01.x, acc[ 6]); FMA2(acc[ 7], d3, b01.y, acc[ 7]);
            FMA2(acc[ 8], d4, b01.x, acc[ 8]); FMA2(acc[ 9], d4, b01.y, acc[ 9]);
            FMA2(acc[10], d5, b01.x, acc[10]); FMA2(acc[11], d5, b01.y, acc[11]);
            FMA2(acc[12], d6, b01.x, acc[12]); FMA2(acc[13], d6, b01.y, acc[13]);
            FMA2(acc[14], d7, b01.x, acc[14]); FMA2(acc[15], d7, b01.y, acc[15]);
        }
    }
    __syncthreads();   // all reads of act complete (part overlaps act)

    // ===== epilogue: relu + masked per-8-row partials =====
    {
        float vf[8];
#pragma unroll
        for (int mi = 0; mi < 8; mi++) vf[mi] = validf[m0 + mi];
#pragma unroll
        for (int oj = 0; oj < 2; oj++){
            float slo = 0.f, shi = 0.f;
#pragma unroll
            for (int mi = 0; mi < 8; mi++){
                float lo, hi;
                UNPACK2(lo, hi, acc[mi*2 + oj]);
                slo += fmaxf(lo, 0.f)*vf[mi];
                shi += fmaxf(hi, 0.f)*vf[mi];
            }
            part[mt*64 + o0 + 2*oj    ] = slo;
            part[mt*64 + o0 + 2*oj + 1] = shi;
        }
    }
    __syncthreads();

    // ===== final: 2-group sum + mean + shortcut + relu =====
#pragma unroll
    for (int s = 0; s < 2; s++){
        const int idx = tid + s*256;        // 512 outputs: 8 points x 64 ch
        const int o   = idx >> 3;
        const int pl  = idx & 7;
        const int pt  = pt0 + pl;
        const int p   = pt & (NP-1);
        float sum = part[(pl*2+0)*64 + o] + part[(pl*2+1)*64 + o];
        float denom = fmaxf(vcnt[pl], 1e-8f);
        float res = fmaxf(sum/denom + g_SC[(size_t)pt*64 + o], 0.f);
        out[((size_t)n*64 + o)*NP + p] = res;
    }
}

// ---------------- launch ----------------
extern "C" void kernel_launch(void* const* d_in, const int* in_sizes, int n_in,
                              void* d_out, int out_size)
{
    const float* feats = (const float*)d_in[0];
    const unsigned char* mask = (const unsigned char*)d_in[1];
    const float* W0 = (const float*)d_in[2];
    const float* W1 = (const float*)d_in[3];
    const float* W2 = (const float*)d_in[4];
    const float* Ws = (const float*)d_in[5];

    cudaFuncSetAttribute(edge_kernel, cudaFuncAttributeMaxDynamicSharedMemorySize, SM_TOTAL);

    fold_kernel<<<16, 256>>>(W0, W1, W2, Ws,
        (const float*)d_in[6],  (const float*)d_in[7],  (const float*)d_in[8],  (const float*)d_in[9],
        (const float*)d_in[10], (const float*)d_in[11], (const float*)d_in[12], (const float*)d_in[13],
        (const float*)d_in[14], (const float*)d_in[15], (const float*)d_in[16], (const float*)d_in[17],
        (const float*)d_in[18], (const float*)d_in[19], (const float*)d_in[20], (const float*)d_in[21]);

    knn_kernel<<<NB*128, 256>>>(feats, mask);
    edge_kernel<<<NB*NP/8, 256, SM_TOTAL>>>((float*)d_out);
}

// round 16
// speedup vs baseline: 1.3277x; 1.3277x over previous
#include <cuda_runtime.h>

#define NB 64
#define NP 1024
#define CF 16
#define KK 16
#define BN_EPS 1e-5f

typedef unsigned long long u64;
typedef unsigned int u32;

#define FMA2(d, a, b, c) \
    asm("fma.rn.f32x2 %0, %1, %2, %3;" : "=l"(d) : "l"(a), "l"(b), "l"(c))
#define PACK2(d, x) \
    asm("mov.b64 %0, {%1, %1};" : "=l"(d) : "f"(x))
#define UNPACK2(lo, hi, v) \
    asm("mov.b64 {%0, %1}, %2;" : "=f"(lo), "=f"(hi) : "l"(v))

// act XOR swizzle: 8-granular, spreads phase-0 scatter across 4x banks.
#define SW(c) ((((c) >> 2) & 3) << 3)

// ---------------- static scratch (no allocations allowed) ----------------
__device__ float g_C [NB*NP*64];
__device__ float g_Y [NB*NP*64];
__device__ float g_SC[NB*NP*64];
__device__ int   g_idx[NB*NP*KK];
__device__ int   g_valid[NB];
__device__ float g_W1t[64*64];     // W1 (BN-scaled), TRANSPOSED [c][o]
__device__ float g_W2t[64*64];
__device__ float g_W0at[CF*64], g_W0bt[CF*64], g_Wst[CF*64];
__device__ float g_t0[64], g_t1[64], g_t2[64], g_ts[64];

// ---------------- fold BN into weights / biases ----------------
__global__ void fold_kernel(const float* __restrict__ W0, const float* __restrict__ W1,
    const float* __restrict__ W2, const float* __restrict__ Ws,
    const float* g0,const float* b0,const float* m0,const float* v0,
    const float* g1,const float* b1,const float* m1,const float* v1,
    const float* g2,const float* b2,const float* m2,const float* v2,
    const float* gs,const float* bs,const float* ms,const float* vs)
{
    int t = blockIdx.x*blockDim.x + threadIdx.x;
    if (t < 64){
        float s0 = g0[t]*rsqrtf(v0[t]+BN_EPS); g_t0[t]=b0[t]-m0[t]*s0;
        float s1 = g1[t]*rsqrtf(v1[t]+BN_EPS); g_t1[t]=b1[t]-m1[t]*s1;
        float s2 = g2[t]*rsqrtf(v2[t]+BN_EPS); g_t2[t]=b2[t]-m2[t]*s2;
        float ss = gs[t]*rsqrtf(vs[t]+BN_EPS); g_ts[t]=bs[t]-ms[t]*ss;
    }
    if (t < 1024){
        int o = t >> 4, c = t & 15;
        float s0 = g0[o]*rsqrtf(v0[o]+BN_EPS);
        float ss = gs[o]*rsqrtf(vs[o]+BN_EPS);
        float wa = W0[o*32 + c], wb = W0[o*32 + 16 + c];
        g_W0at[c*64 + o] = (wa + wb)*s0;
        g_W0bt[c*64 + o] = wb*s0;
        g_Wst [c*64 + o] = Ws[o*16 + c]*ss;
    }
    if (t < 4096){
        int oo = t >> 6, cc = t & 63;
        g_W1t[cc*64 + oo] = W1[t]*(g1[oo]*rsqrtf(v1[oo]+BN_EPS));
        g_W2t[cc*64 + oo] = W2[t]*(g2[oo]*rsqrtf(v2[oo]+BN_EPS));
    }
}

// ---------------- KNN + fused prep: warp-per-point, in-register merge ----------------
// Per-lane bitonic sort of 32 candidates, then 5 halving rounds of cross-lane
// bitonic top-16 merge (16 independent shfls + 16 min + 32-CE half-cleaner per
// round). No heads SMEM, ~450-cycle critical path (was ~2080 via shfl-reduce).
__global__ void __launch_bounds__(256)
knn_kernel(const float* __restrict__ feats,
           const unsigned char* __restrict__ mask)
{
    const int n    = blockIdx.x >> 7;
    const int bloc = blockIdx.x & 127;
    const int warp = threadIdx.x >> 5;
    const int lane = threadIdx.x & 31;
    const int p    = bloc*8 + warp;

    __shared__ float px[NP], py[NP], rr[NP];
    __shared__ float sx[8][CF];
    __shared__ int scnt;

    if (threadIdx.x == 0) scnt = 0;
    int mcnt = 0;
    for (int i = threadIdx.x; i < NP; i += 256){
        float2 xy = __ldg((const float2*)&feats[(n*NP + i)*(2+CF)]);
        px[i] = xy.x; py[i] = xy.y; rr[i] = xy.x*xy.x + xy.y*xy.y;
        if (bloc == 0 && mask[n*NP + i]) mcnt++;
    }
    if (threadIdx.x < 128){
        int lp = threadIdx.x >> 4, c = threadIdx.x & 15;
        sx[lp][c] = feats[(n*NP + bloc*8 + lp)*(2+CF) + 2 + c];
    }
    __syncthreads();
    if (bloc == 0 && mcnt) atomicAdd(&scnt, mcnt);

    const float xp = px[p], yp = py[p], rp = rr[p];
    const float nx = -2.f*xp, ny = -2.f*yp;

    u32 key[32];
#pragma unroll
    for (int i = 0; i < 32; i++){
        int q = i*32 + lane;
        float d = fmaxf(fmaf(nx, px[q], fmaf(ny, py[q], rp + rr[q])), 0.f);
        u32 kb = (__float_as_uint(d) & 0xFFFFFC00u) | (u32)q;
        key[i] = (q == p) ? 0xFFFFFFFFu : kb;
    }

    // in-register bitonic sort of 32, ascending
#pragma unroll
    for (int kk = 2; kk <= 32; kk <<= 1){
#pragma unroll
        for (int j = kk >> 1; j > 0; j >>= 1){
#pragma unroll
            for (int i = 0; i < 32; i++){
                int l = i ^ j;
                if (l > i){
                    u32 a = key[i], b = key[l];
                    u32 lo = a < b ? a : b;
                    u32 hi = a < b ? b : a;
                    if ((i & kk) == 0){ key[i] = lo; key[l] = hi; }
                    else              { key[i] = hi; key[l] = lo; }
                }
            }
        }
    }

    // cross-lane top-16 merge: 5 halving rounds, all in registers
    u32 a[16];
#pragma unroll
    for (int j = 0; j < 16; j++) a[j] = key[j];
#pragma unroll
    for (int d = 16; d >= 1; d >>= 1){
        u32 b[16];
#pragma unroll
        for (int j = 0; j < 16; j++) b[j] = __shfl_xor_sync(0xFFFFFFFFu, a[j], d);
        u32 m[16];
#pragma unroll
        for (int j = 0; j < 16; j++){
            u32 x = a[j], y = b[15 - j];
            m[j] = (x < y) ? x : y;          // 16 smallest of union, bitonic
        }
        // half-cleaner: sort the bitonic 16 ascending
#pragma unroll
        for (int s = 8; s >= 1; s >>= 1){
#pragma unroll
            for (int i = 0; i < 16; i++){
                int l = i | s;
                if ((i & s) == 0 && l < 16){
                    u32 x = m[i], y = m[l];
                    u32 lo = (x < y) ? x : y;
                    u32 hi = (x < y) ? y : x;
                    m[i] = lo; m[l] = hi;
                }
            }
        }
#pragma unroll
        for (int j = 0; j < 16; j++) a[j] = m[j];
    }

    if (lane == 0){
        int4* dst = (int4*)(g_idx + (n*NP + p)*KK);
        dst[0] = make_int4((int)(a[ 0]&1023u), (int)(a[ 1]&1023u), (int)(a[ 2]&1023u), (int)(a[ 3]&1023u));
        dst[1] = make_int4((int)(a[ 4]&1023u), (int)(a[ 5]&1023u), (int)(a[ 6]&1023u), (int)(a[ 7]&1023u));
        dst[2] = make_int4((int)(a[ 8]&1023u), (int)(a[ 9]&1023u), (int)(a[10]&1023u), (int)(a[11]&1023u));
        dst[3] = make_int4((int)(a[12]&1023u), (int)(a[13]&1023u), (int)(a[14]&1023u), (int)(a[15]&1023u));
    }

    // ---- fused prep: per-point projections C, Y, shortcut ----
#pragma unroll
    for (int s = 0; s < 2; s++){
        const int idx = threadIdx.x + s*256;
        const int lp  = idx >> 6;
        const int o   = idx & 63;
        float av = 0.f, yb = 0.f, sc = 0.f;
#pragma unroll
        for (int c = 0; c < CF; c++){
            float x = sx[lp][c];
            av = fmaf(x, g_W0at[c*64 + o], av);
            yb = fmaf(x, g_W0bt[c*64 + o], yb);
            sc = fmaf(x, g_Wst [c*64 + o], sc);
        }
        const int pt = n*NP + bloc*8 + lp;
        g_C[(size_t)pt*64 + o] = av + g_t0[o];
        g_Y[(size_t)pt*64 + o] = yb;
        float scv = sc + g_ts[o];
        if (mask[pt]) scv = 0.f;
        g_SC[(size_t)pt*64 + o] = scv;
    }

    if (bloc == 0){
        __syncthreads();
        if (threadIdx.x == 0) g_valid[n] = NP - scnt;
    }
}

// ---------------- edge kernel (R14, best): XOR-swizzled act + 8Mx8N SMEM-weight GEMM ----------------
#define SM_ACT    0                    // 64*128 floats = 32768 B (part overlaps)
#define SM_W      32768                // 64*64 floats = 16384 B
#define SM_VALIDF 49152                // 128 floats
#define SM_VCNT   49664                // 8 floats
#define SM_TOTAL  49696

__global__ void __launch_bounds__(128)
edge_kernel(float* __restrict__ out)
{
    extern __shared__ char smraw[];
    float* act    = (float*)(smraw + SM_ACT);
    float* wsm    = (float*)(smraw + SM_W);
    float* part   = (float*)(smraw + SM_ACT);     // overlaps act (used after L2)
    float* validf = (float*)(smraw + SM_VALIDF);
    float* vcnt   = (float*)(smraw + SM_VCNT);

    const int tid  = threadIdx.x;
    const int lane = tid & 31;
    const int w    = tid >> 5;
    const int pt0  = blockIdx.x * 8;
    const int n    = pt0 >> 10;

    const int valid = g_valid[n];

    // ---- stage W1 ----
    {
        const float4* src = (const float4*)g_W1t;
        float4* dst = (float4*)wsm;
#pragma unroll
        for (int i = 0; i < 8; i++) dst[tid + i*128] = __ldg(src + tid + i*128);
    }

    // ---- phase 0: coalesced Y/C gather, swizzled scatter into act ----
    {
        const int half  = lane >> 4;
        const int chunk = lane & 15;
        const int sw    = (chunk & 3) << 3;  // == SW(chunk*4 + j) for j<4
#pragma unroll 4
        for (int i = 0; i < 16; i++){
            const int e  = w*32 + i*2 + half;
            const int pt = pt0 + (e >> 4);
            const int q  = __ldg(&g_idx[pt*KK + (e & 15)]);
            if (chunk == 0) validf[e] = (q < valid) ? 1.f : 0.f;
            float4 y  = __ldg((const float4*)(g_Y + ((size_t)n*NP + q)*64) + chunk);
            float4 c4 = __ldg((const float4*)(g_C + (size_t)pt*64) + chunk);
            const int cc = chunk*4;
            const int es = e ^ sw;
            act[(cc+0)*128 + es] = fmaxf(c4.x - y.x, 0.f);
            act[(cc+1)*128 + es] = fmaxf(c4.y - y.y, 0.f);
            act[(cc+2)*128 + es] = fmaxf(c4.z - y.z, 0.f);
            act[(cc+3)*128 + es] = fmaxf(c4.w - y.w, 0.f);
        }
    }
    __syncthreads();

    if (tid < 8){
        float s = 0.f;
#pragma unroll
        for (int j = 0; j < 16; j++) s += validf[tid*16 + j];
        vcnt[tid] = s;
    }

    // ---- tiling: 16 M-tiles x 8 N-tiles; thread = 8M x 8N ----
    const int mt = tid & 15;
    const int nt = tid >> 4;
    const int m0 = mt * 8;
    const int o0 = nt * 8;

    u64 acc[32];   // acc[mi*4 + oj] = packed (o0+2oj, o0+2oj+1) for row m0+mi

    // ===== layer 1 =====
    {
        const u64* tp = (const u64*)(g_t1 + o0);
        u64 t0p = tp[0], t1p = tp[1], t2p = tp[2], t3p = tp[3];
#pragma unroll
        for (int mi = 0; mi < 8; mi++){
            acc[mi*4+0]=t0p; acc[mi*4+1]=t1p; acc[mi*4+2]=t2p; acc[mi*4+3]=t3p;
        }
        const float* W = wsm + o0;
#pragma unroll 4
        for (int c = 0; c < 64; c++){
            const float* A = act + c*128 + (m0 ^ SW(c));
            float4 a0 = *(const float4*)(A);
            float4 a1 = *(const float4*)(A + 4);
            ulonglong2 b01 = *(const ulonglong2*)(W + c*64);
            ulonglong2 b23 = *(const ulonglong2*)(W + c*64 + 4);
            u64 d0,d1,d2,d3,d4,d5,d6,d7;
            PACK2(d0, a0.x); PACK2(d1, a0.y); PACK2(d2, a0.z); PACK2(d3, a0.w);
            PACK2(d4, a1.x); PACK2(d5, a1.y); PACK2(d6, a1.z); PACK2(d7, a1.w);
            FMA2(acc[ 0], d0, b01.x, acc[ 0]); FMA2(acc[ 1], d0, b01.y, acc[ 1]);
            FMA2(acc[ 2], d0, b23.x, acc[ 2]); FMA2(acc[ 3], d0, b23.y, acc[ 3]);
            FMA2(acc[ 4], d1, b01.x, acc[ 4]); FMA2(acc[ 5], d1, b01.y, acc[ 5]);
            FMA2(acc[ 6], d1, b23.x, acc[ 6]); FMA2(acc[ 7], d1, b23.y, acc[ 7]);
            FMA2(acc[ 8], d2, b01.x, acc[ 8]); FMA2(acc[ 9], d2, b01.y, acc[ 9]);
            FMA2(acc[10], d2, b23.x, acc[10]); FMA2(acc[11], d2, b23.y, acc[11]);
            FMA2(acc[12], d3, b01.x, acc[12]); FMA2(acc[13], d3, b01.y, acc[13]);
            FMA2(acc[14], d3, b23.x, acc[14]); FMA2(acc[15], d3, b23.y, acc[15]);
            FMA2(acc[16], d4, b01.x, acc[16]); FMA2(acc[17], d4, b01.y, acc[17]);
            FMA2(acc[18], d4, b23.x, acc[18]); FMA2(acc[19], d4, b23.y, acc[19]);
            FMA2(acc[20], d5, b01.x, acc[20]); FMA2(acc[21], d5, b01.y, acc[21]);
            FMA2(acc[22], d5, b23.x, acc[22]); FMA2(acc[23], d5, b23.y, acc[23]);
            FMA2(acc[24], d6, b01.x, acc[24]); FMA2(acc[25], d6, b01.y, acc[25]);
            FMA2(acc[26], d6, b23.x, acc[26]); FMA2(acc[27], d6, b23.y, acc[27]);
            FMA2(acc[28], d7, b01.x, acc[28]); FMA2(acc[29], d7, b01.y, acc[29]);
            FMA2(acc[30], d7, b23.x, acc[30]); FMA2(acc[31], d7, b23.y, acc[31]);
        }
    }
    __syncthreads();   // all reads of act + wsm(W1) complete

    // relu + transposed writeback (swizzled); stage W2
#pragma unroll
    for (int oj = 0; oj < 4; oj++){
        float lo[8], hi[8];
#pragma unroll
        for (int mi = 0; mi < 8; mi++) UNPACK2(lo[mi], hi[mi], acc[mi*4 + oj]);
        float4 vl0 = { fmaxf(lo[0],0.f), fmaxf(lo[1],0.f), fmaxf(lo[2],0.f), fmaxf(lo[3],0.f) };
        float4 vl1 = { fmaxf(lo[4],0.f), fmaxf(lo[5],0.f), fmaxf(lo[6],0.f), fmaxf(lo[7],0.f) };
        float4 vh0 = { fmaxf(hi[0],0.f), fmaxf(hi[1],0.f), fmaxf(hi[2],0.f), fmaxf(hi[3],0.f) };
        float4 vh1 = { fmaxf(hi[4],0.f), fmaxf(hi[5],0.f), fmaxf(hi[6],0.f), fmaxf(hi[7],0.f) };
        const int olo = o0 + 2*oj;
        const int ms  = m0 ^ SW(olo);
        *(float4*)(act + (olo    )*128 + ms    ) = vl0;
        *(float4*)(act + (olo    )*128 + ms + 4) = vl1;
        *(float4*)(act + (olo + 1)*128 + ms    ) = vh0;
        *(float4*)(act + (olo + 1)*128 + ms + 4) = vh1;
    }
    {
        const float4* src = (const float4*)g_W2t;
        float4* dst = (float4*)wsm;
#pragma unroll
        for (int i = 0; i < 8; i++) dst[tid + i*128] = __ldg(src + tid + i*128);
    }
    __syncthreads();   // layer-1 activations + W2 ready

    // ===== layer 2 =====
    {
        const u64* tp = (const u64*)(g_t2 + o0);
        u64 t0p = tp[0], t1p = tp[1], t2p = tp[2], t3p = tp[3];
#pragma unroll
        for (int mi = 0; mi < 8; mi++){
            acc[mi*4+0]=t0p; acc[mi*4+1]=t1p; acc[mi*4+2]=t2p; acc[mi*4+3]=t3p;
        }
        const float* W = wsm + o0;
#pragma unroll 4
        for (int c = 0; c < 64; c++){
            const float* A = act + c*128 + (m0 ^ SW(c));
            float4 a0 = *(const float4*)(A);
            float4 a1 = *(const float4*)(A + 4);
            ulonglong2 b01 = *(const ulonglong2*)(W + c*64);
            ulonglong2 b23 = *(const ulonglong2*)(W + c*64 + 4);
            u64 d0,d1,d2,d3,d4,d5,d6,d7;
            PACK2(d0, a0.x); PACK2(d1, a0.y); PACK2(d2, a0.z); PACK2(d3, a0.w);
            PACK2(d4, a1.x); PACK2(d5, a1.y); PACK2(d6, a1.z); PACK2(d7, a1.w);
            FMA2(acc[ 0], d0, b01.x, acc[ 0]); FMA2(acc[ 1], d0, b01.y, acc[ 1]);
            FMA2(acc[ 2], d0, b23.x, acc[ 2]); FMA2(acc[ 3], d0, b23.y, acc[ 3]);
            FMA2(acc[ 4], d1, b01.x, acc[ 4]); FMA2(acc[ 5], d1, b01.y, acc[ 5]);
            FMA2(acc[ 6], d1, b23.x, acc[ 6]); FMA2(acc[ 7], d1, b23.y, acc[ 7]);
            FMA2(acc[ 8], d2, b01.x, acc[ 8]); FMA2(acc[ 9], d2, b01.y, acc[ 9]);
            FMA2(acc[10], d2, b23.x, acc[10]); FMA2(acc[11], d2, b23.y, acc[11]);
            FMA2(acc[12], d3, b01.x, acc[12]); FMA2(acc[13], d3, b01.y, acc[13]);
            FMA2(acc[14], d3, b23.x, acc[14]); FMA2(acc[15], d3, b23.y, acc[15]);
            FMA2(acc[16], d4, b01.x, acc[16]); FMA2(acc[17], d4, b01.y, acc[17]);
            FMA2(acc[18], d4, b23.x, acc[18]); FMA2(acc[19], d4, b23.y, acc[19]);
            FMA2(acc[20], d5, b01.x, acc[20]); FMA2(acc[21], d5, b01.y, acc[21]);
            FMA2(acc[22], d5, b23.x, acc[22]); FMA2(acc[23], d5, b23.y, acc[23]);
            FMA2(acc[24], d6, b01.x, acc[24]); FMA2(acc[25], d6, b01.y, acc[25]);
            FMA2(acc[26], d6, b23.x, acc[26]); FMA2(acc[27], d6, b23.y, acc[27]);
            FMA2(acc[28], d7, b01.x, acc[28]); FMA2(acc[29], d7, b01.y, acc[29]);
            FMA2(acc[30], d7, b23.x, acc[30]); FMA2(acc[31], d7, b23.y, acc[31]);
        }
    }
    __syncthreads();   // all reads of act complete (part overlaps act)

    // ===== epilogue: relu + masked per-8-row-group partials =====
    {
        float vf[8];
#pragma unroll
        for (int mi = 0; mi < 8; mi++) vf[mi] = validf[m0 + mi];
#pragma unroll
        for (int oj = 0; oj < 4; oj++){
            float slo = 0.f, shi = 0.f;
#pragma unroll
            for (int mi = 0; mi < 8; mi++){
                float lo, hi;
                UNPACK2(lo, hi, acc[mi*4 + oj]);
                slo += fmaxf(lo, 0.f)*vf[mi];
                shi += fmaxf(hi, 0.f)*vf[mi];
            }
            part[mt*64 + o0 + 2*oj    ] = slo;
            part[mt*64 + o0 + 2*oj + 1] = shi;
        }
    }
    __syncthreads();

    // ===== final: 2-group sum + mean + shortcut + relu =====
#pragma unroll
    for (int s = 0; s < 4; s++){
        const int idx = tid + s*128;        // 512 outputs: 8 points x 64 ch
        const int o   = idx >> 3;
        const int pl  = idx & 7;
        const int pt  = pt0 + pl;
        const int p   = pt & (NP-1);
        float sum = part[(pl*2+0)*64 + o] + part[(pl*2+1)*64 + o];
        float denom = fmaxf(vcnt[pl], 1e-8f);
        float res = fmaxf(sum/denom + g_SC[(size_t)pt*64 + o], 0.f);
        out[((size_t)n*64 + o)*NP + p] = res;
    }
}

// ---------------- launch ----------------
extern "C" void kernel_launch(void* const* d_in, const int* in_sizes, int n_in,
                              void* d_out, int out_size)
{
    const float* feats = (const float*)d_in[0];
    const unsigned char* mask = (const unsigned char*)d_in[1];
    const float* W0 = (const float*)d_in[2];
    const float* W1 = (const float*)d_in[3];
    const float* W2 = (const float*)d_in[4];
    const float* Ws = (const float*)d_in[5];

    cudaFuncSetAttribute(edge_kernel, cudaFuncAttributeMaxDynamicSharedMemorySize, SM_TOTAL);

    fold_kernel<<<16, 256>>>(W0, W1, W2, Ws,
        (const float*)d_in[6],  (const float*)d_in[7],  (const float*)d_in[8],  (const float*)d_in[9],
        (const float*)d_in[10], (const float*)d_in[11], (const float*)d_in[12], (const float*)d_in[13],
        (const float*)d_in[14], (const float*)d_in[15], (const float*)d_in[16], (const float*)d_in[17],
        (const float*)d_in[18], (const float*)d_in[19], (const float*)d_in[20], (const float*)d_in[21]);

    knn_kernel<<<NB*128, 256>>>(feats, mask);
    edge_kernel<<<NB*NP/8, 128, SM_TOTAL>>>((float*)d_out);
}

// round 17
// speedup vs baseline: 1.4066x; 1.0594x over previous
#include <cuda_runtime.h>

#define NB 64
#define NP 1024
#define CF 16
#define KK 16
#define BN_EPS 1e-5f

typedef unsigned long long u64;
typedef unsigned int u32;

#define FMA2(d, a, b, c) \
    asm("fma.rn.f32x2 %0, %1, %2, %3;" : "=l"(d) : "l"(a), "l"(b), "l"(c))
#define PACK2(d, x) \
    asm("mov.b64 %0, {%1, %1};" : "=l"(d) : "f"(x))
#define UNPACK2(lo, hi, v) \
    asm("mov.b64 {%0, %1}, %2;" : "=f"(lo), "=f"(hi) : "l"(v))

// act XOR swizzle: 8-granular, spreads phase-0 scatter across 4x banks.
#define SW(c) ((((c) >> 2) & 3) << 3)

// ---------------- static scratch (no allocations allowed) ----------------
__device__ float g_C [NB*NP*64];
__device__ float g_Y [NB*NP*64];
__device__ float g_SC[NB*NP*64];
__device__ int   g_idx[NB*NP*KK];
__device__ int   g_valid[NB];
__device__ float2 g_pxy[NB*NP];    // packed point coords
__device__ float  g_rr [NB*NP];    // |p|^2
__device__ float g_W1t[64*64];     // W1 (BN-scaled), TRANSPOSED [c][o]
__device__ float g_W2t[64*64];
__device__ float g_W0at[CF*64], g_W0bt[CF*64], g_Wst[CF*64];
__device__ float g_t0[64], g_t1[64], g_t2[64], g_ts[64];

// ---------------- fold BN into weights / biases ----------------
__global__ void fold_kernel(const float* __restrict__ W0, const float* __restrict__ W1,
    const float* __restrict__ W2, const float* __restrict__ Ws,
    const float* g0,const float* b0,const float* m0,const float* v0,
    const float* g1,const float* b1,const float* m1,const float* v1,
    const float* g2,const float* b2,const float* m2,const float* v2,
    const float* gs,const float* bs,const float* ms,const float* vs)
{
    int t = blockIdx.x*blockDim.x + threadIdx.x;
    if (t < 64){
        float s0 = g0[t]*rsqrtf(v0[t]+BN_EPS); g_t0[t]=b0[t]-m0[t]*s0;
        float s1 = g1[t]*rsqrtf(v1[t]+BN_EPS); g_t1[t]=b1[t]-m1[t]*s1;
        float s2 = g2[t]*rsqrtf(v2[t]+BN_EPS); g_t2[t]=b2[t]-m2[t]*s2;
        float ss = gs[t]*rsqrtf(vs[t]+BN_EPS); g_ts[t]=bs[t]-ms[t]*ss;
    }
    if (t < 1024){
        int o = t >> 4, c = t & 15;
        float s0 = g0[o]*rsqrtf(v0[o]+BN_EPS);
        float ss = gs[o]*rsqrtf(vs[o]+BN_EPS);
        float wa = W0[o*32 + c], wb = W0[o*32 + 16 + c];
        g_W0at[c*64 + o] = (wa + wb)*s0;
        g_W0bt[c*64 + o] = wb*s0;
        g_Wst [c*64 + o] = Ws[o*16 + c]*ss;
    }
    if (t < 4096){
        int oo = t >> 6, cc = t & 63;
        g_W1t[cc*64 + oo] = W1[t]*(g1[oo]*rsqrtf(v1[oo]+BN_EPS));
        g_W2t[cc*64 + oo] = W2[t]*(g2[oo]*rsqrtf(v2[oo]+BN_EPS));
    }
}

// ---------------- pack: feats -> packed coords + rr + valid count ----------------
// One block per batch: the stride-72B feats traversal happens ONCE per batch
// (was 128x inside knn blocks).
__global__ void pack_kernel(const float* __restrict__ feats,
                            const unsigned char* __restrict__ mask)
{
    const int n = blockIdx.x;
    __shared__ int scnt;
    if (threadIdx.x == 0) scnt = 0;
    __syncthreads();
    int mcnt = 0;
    for (int i = threadIdx.x; i < NP; i += 256){
        float2 xy = __ldg((const float2*)&feats[(n*NP + i)*(2+CF)]);
        g_pxy[n*NP + i] = xy;
        g_rr [n*NP + i] = xy.x*xy.x + xy.y*xy.y;
        if (mask[n*NP + i]) mcnt++;
    }
    if (mcnt) atomicAdd(&scnt, mcnt);
    __syncthreads();
    if (threadIdx.x == 0) g_valid[n] = NP - scnt;
}

// ---------------- KNN + fused prep: warp-per-point bitonic + heads merge ----------------
__global__ void __launch_bounds__(256)
knn_kernel(const float* __restrict__ feats,
           const unsigned char* __restrict__ mask)
{
    const int n    = blockIdx.x >> 7;
    const int bloc = blockIdx.x & 127;
    const int warp = threadIdx.x >> 5;
    const int lane = threadIdx.x & 31;
    const int p    = bloc*8 + warp;

    __shared__ float px[NP], py[NP], rr[NP];
    __shared__ u32 heads[8][512];
    __shared__ float sx[8][CF];

    // coalesced staging from packed arrays (96 wf vs 2300 for strided feats)
    for (int i = threadIdx.x; i < NP; i += 256){
        float2 xy = __ldg(&g_pxy[n*NP + i]);
        px[i] = xy.x; py[i] = xy.y;
        rr[i] = __ldg(&g_rr[n*NP + i]);
    }
    if (threadIdx.x < 128){
        int lp = threadIdx.x >> 4, c = threadIdx.x & 15;
        sx[lp][c] = feats[(n*NP + bloc*8 + lp)*(2+CF) + 2 + c];
    }
    __syncthreads();

    const float xp = px[p], yp = py[p], rp = rr[p];
    const float nx = -2.f*xp, ny = -2.f*yp;

    u32 key[32];
#pragma unroll
    for (int i = 0; i < 32; i++){
        int q = i*32 + lane;
        float d = fmaxf(fmaf(nx, px[q], fmaf(ny, py[q], rp + rr[q])), 0.f);
        u32 kb = (__float_as_uint(d) & 0xFFFFFC00u) | (u32)q;
        key[i] = (q == p) ? 0xFFFFFFFFu : kb;
    }
#pragma unroll
    for (int kk = 2; kk <= 32; kk <<= 1){
#pragma unroll
        for (int j = kk >> 1; j > 0; j >>= 1){
#pragma unroll
            for (int i = 0; i < 32; i++){
                int l = i ^ j;
                if (l > i){
                    u32 a = key[i], b = key[l];
                    u32 lo = a < b ? a : b;
                    u32 hi = a < b ? b : a;
                    if ((i & kk) == 0){ key[i] = lo; key[l] = hi; }
                    else              { key[i] = hi; key[l] = lo; }
                }
            }
        }
    }
#pragma unroll
    for (int j = 0; j < 16; j++) heads[warp][j*32 + lane] = key[j];

    int ptr = 0;
    u32 sel = 0;
#pragma unroll 1
    for (int r = 0; r < KK; r++){
        u32 h = (ptr < 16) ? heads[warp][ptr*32 + lane] : 0xFFFFFFFFu;
        u32 w = h;
#pragma unroll
        for (int d = 16; d; d >>= 1){
            u32 o = __shfl_xor_sync(0xFFFFFFFFu, w, d);
            w = (o < w) ? o : w;
        }
        if (h == w) ptr++;
        if (lane == r) sel = w;
    }
    if (lane < KK) g_idx[(n*NP + p)*KK + lane] = (int)(sel & 1023u);

    // ---- fused prep: per-point projections C, Y, shortcut ----
#pragma unroll
    for (int s = 0; s < 2; s++){
        const int idx = threadIdx.x + s*256;
        const int lp  = idx >> 6;
        const int o   = idx & 63;
        float av = 0.f, yb = 0.f, sc = 0.f;
#pragma unroll
        for (int c = 0; c < CF; c++){
            float x = sx[lp][c];
            av = fmaf(x, g_W0at[c*64 + o], av);
            yb = fmaf(x, g_W0bt[c*64 + o], yb);
            sc = fmaf(x, g_Wst [c*64 + o], sc);
        }
        const int pt = n*NP + bloc*8 + lp;
        g_C[(size_t)pt*64 + o] = av + g_t0[o];
        g_Y[(size_t)pt*64 + o] = yb;
        float scv = sc + g_ts[o];
        if (mask[pt]) scv = 0.f;
        g_SC[(size_t)pt*64 + o] = scv;
    }
}

// ---------------- edge kernel (R14, best): XOR-swizzled act + 8Mx8N SMEM-weight GEMM ----------------
#define SM_ACT    0                    // 64*128 floats = 32768 B (part overlaps)
#define SM_W      32768                // 64*64 floats = 16384 B
#define SM_VALIDF 49152                // 128 floats
#define SM_VCNT   49664                // 8 floats
#define SM_TOTAL  49696

__global__ void __launch_bounds__(128)
edge_kernel(float* __restrict__ out)
{
    extern __shared__ char smraw[];
    float* act    = (float*)(smraw + SM_ACT);
    float* wsm    = (float*)(smraw + SM_W);
    float* part   = (float*)(smraw + SM_ACT);     // overlaps act (used after L2)
    float* validf = (float*)(smraw + SM_VALIDF);
    float* vcnt   = (float*)(smraw + SM_VCNT);

    const int tid  = threadIdx.x;
    const int lane = tid & 31;
    const int w    = tid >> 5;
    const int pt0  = blockIdx.x * 8;
    const int n    = pt0 >> 10;

    const int valid = g_valid[n];

    // ---- stage W1 ----
    {
        const float4* src = (const float4*)g_W1t;
        float4* dst = (float4*)wsm;
#pragma unroll
        for (int i = 0; i < 8; i++) dst[tid + i*128] = __ldg(src + tid + i*128);
    }

    // ---- phase 0: coalesced Y/C gather, swizzled scatter into act ----
    {
        const int half  = lane >> 4;
        const int chunk = lane & 15;
        const int sw    = (chunk & 3) << 3;  // == SW(chunk*4 + j) for j<4
#pragma unroll 4
        for (int i = 0; i < 16; i++){
            const int e  = w*32 + i*2 + half;
            const int pt = pt0 + (e >> 4);
            const int q  = __ldg(&g_idx[pt*KK + (e & 15)]);
            if (chunk == 0) validf[e] = (q < valid) ? 1.f : 0.f;
            float4 y  = __ldg((const float4*)(g_Y + ((size_t)n*NP + q)*64) + chunk);
            float4 c4 = __ldg((const float4*)(g_C + (size_t)pt*64) + chunk);
            const int cc = chunk*4;
            const int es = e ^ sw;
            act[(cc+0)*128 + es] = fmaxf(c4.x - y.x, 0.f);
            act[(cc+1)*128 + es] = fmaxf(c4.y - y.y, 0.f);
            act[(cc+2)*128 + es] = fmaxf(c4.z - y.z, 0.f);
            act[(cc+3)*128 + es] = fmaxf(c4.w - y.w, 0.f);
        }
    }
    __syncthreads();

    if (tid < 8){
        float s = 0.f;
#pragma unroll
        for (int j = 0; j < 16; j++) s += validf[tid*16 + j];
        vcnt[tid] = s;
    }

    // ---- tiling: 16 M-tiles x 8 N-tiles; thread = 8M x 8N ----
    const int mt = tid & 15;
    const int nt = tid >> 4;
    const int m0 = mt * 8;
    const int o0 = nt * 8;

    u64 acc[32];   // acc[mi*4 + oj] = packed (o0+2oj, o0+2oj+1) for row m0+mi

    // ===== layer 1 =====
    {
        const u64* tp = (const u64*)(g_t1 + o0);
        u64 t0p = tp[0], t1p = tp[1], t2p = tp[2], t3p = tp[3];
#pragma unroll
        for (int mi = 0; mi < 8; mi++){
            acc[mi*4+0]=t0p; acc[mi*4+1]=t1p; acc[mi*4+2]=t2p; acc[mi*4+3]=t3p;
        }
        const float* W = wsm + o0;
#pragma unroll 4
        for (int c = 0; c < 64; c++){
            const float* A = act + c*128 + (m0 ^ SW(c));
            float4 a0 = *(const float4*)(A);
            float4 a1 = *(const float4*)(A + 4);
            ulonglong2 b01 = *(const ulonglong2*)(W + c*64);
            ulonglong2 b23 = *(const ulonglong2*)(W + c*64 + 4);
            u64 d0,d1,d2,d3,d4,d5,d6,d7;
            PACK2(d0, a0.x); PACK2(d1, a0.y); PACK2(d2, a0.z); PACK2(d3, a0.w);
            PACK2(d4, a1.x); PACK2(d5, a1.y); PACK2(d6, a1.z); PACK2(d7, a1.w);
            FMA2(acc[ 0], d0, b01.x, acc[ 0]); FMA2(acc[ 1], d0, b01.y, acc[ 1]);
            FMA2(acc[ 2], d0, b23.x, acc[ 2]); FMA2(acc[ 3], d0, b23.y, acc[ 3]);
            FMA2(acc[ 4], d1, b01.x, acc[ 4]); FMA2(acc[ 5], d1, b01.y, acc[ 5]);
            FMA2(acc[ 6], d1, b23.x, acc[ 6]); FMA2(acc[ 7], d1, b23.y, acc[ 7]);
            FMA2(acc[ 8], d2, b01.x, acc[ 8]); FMA2(acc[ 9], d2, b01.y, acc[ 9]);
            FMA2(acc[10], d2, b23.x, acc[10]); FMA2(acc[11], d2, b23.y, acc[11]);
            FMA2(acc[12], d3, b01.x, acc[12]); FMA2(acc[13], d3, b01.y, acc[13]);
            FMA2(acc[14], d3, b23.x, acc[14]); FMA2(acc[15], d3, b23.y, acc[15]);
            FMA2(acc[16], d4, b01.x, acc[16]); FMA2(acc[17], d4, b01.y, acc[17]);
            FMA2(acc[18], d4, b23.x, acc[18]); FMA2(acc[19], d4, b23.y, acc[19]);
            FMA2(acc[20], d5, b01.x, acc[20]); FMA2(acc[21], d5, b01.y, acc[21]);
            FMA2(acc[22], d5, b23.x, acc[22]); FMA2(acc[23], d5, b23.y, acc[23]);
            FMA2(acc[24], d6, b01.x, acc[24]); FMA2(acc[25], d6, b01.y, acc[25]);
            FMA2(acc[26], d6, b23.x, acc[26]); FMA2(acc[27], d6, b23.y, acc[27]);
            FMA2(acc[28], d7, b01.x, acc[28]); FMA2(acc[29], d7, b01.y, acc[29]);
            FMA2(acc[30], d7, b23.x, acc[30]); FMA2(acc[31], d7, b23.y, acc[31]);
        }
    }
    __syncthreads();   // all reads of act + wsm(W1) complete

    // relu + transposed writeback (swizzled); stage W2
#pragma unroll
    for (int oj = 0; oj < 4; oj++){
        float lo[8], hi[8];
#pragma unroll
        for (int mi = 0; mi < 8; mi++) UNPACK2(lo[mi], hi[mi], acc[mi*4 + oj]);
        float4 vl0 = { fmaxf(lo[0],0.f), fmaxf(lo[1],0.f), fmaxf(lo[2],0.f), fmaxf(lo[3],0.f) };
        float4 vl1 = { fmaxf(lo[4],0.f), fmaxf(lo[5],0.f), fmaxf(lo[6],0.f), fmaxf(lo[7],0.f) };
        float4 vh0 = { fmaxf(hi[0],0.f), fmaxf(hi[1],0.f), fmaxf(hi[2],0.f), fmaxf(hi[3],0.f) };
        float4 vh1 = { fmaxf(hi[4],0.f), fmaxf(hi[5],0.f), fmaxf(hi[6],0.f), fmaxf(hi[7],0.f) };
        const int olo = o0 + 2*oj;
        const int ms  = m0 ^ SW(olo);
        *(float4*)(act + (olo    )*128 + ms    ) = vl0;
        *(float4*)(act + (olo    )*128 + ms + 4) = vl1;
        *(float4*)(act + (olo + 1)*128 + ms    ) = vh0;
        *(float4*)(act + (olo + 1)*128 + ms + 4) = vh1;
    }
    {
        const float4* src = (const float4*)g_W2t;
        float4* dst = (float4*)wsm;
#pragma unroll
        for (int i = 0; i < 8; i++) dst[tid + i*128] = __ldg(src + tid + i*128);
    }
    __syncthreads();   // layer-1 activations + W2 ready

    // ===== layer 2 =====
    {
        const u64* tp = (const u64*)(g_t2 + o0);
        u64 t0p = tp[0], t1p = tp[1], t2p = tp[2], t3p = tp[3];
#pragma unroll
        for (int mi = 0; mi < 8; mi++){
            acc[mi*4+0]=t0p; acc[mi*4+1]=t1p; acc[mi*4+2]=t2p; acc[mi*4+3]=t3p;
        }
        const float* W = wsm + o0;
#pragma unroll 4
        for (int c = 0; c < 64; c++){
            const float* A = act + c*128 + (m0 ^ SW(c));
            float4 a0 = *(const float4*)(A);
            float4 a1 = *(const float4*)(A + 4);
            ulonglong2 b01 = *(const ulonglong2*)(W + c*64);
            ulonglong2 b23 = *(const ulonglong2*)(W + c*64 + 4);
            u64 d0,d1,d2,d3,d4,d5,d6,d7;
            PACK2(d0, a0.x); PACK2(d1, a0.y); PACK2(d2, a0.z); PACK2(d3, a0.w);
            PACK2(d4, a1.x); PACK2(d5, a1.y); PACK2(d6, a1.z); PACK2(d7, a1.w);
            FMA2(acc[ 0], d0, b01.x, acc[ 0]); FMA2(acc[ 1], d0, b01.y, acc[ 1]);
            FMA2(acc[ 2], d0, b23.x, acc[ 2]); FMA2(acc[ 3], d0, b23.y, acc[ 3]);
            FMA2(acc[ 4], d1, b01.x, acc[ 4]); FMA2(acc[ 5], d1, b01.y, acc[ 5]);
            FMA2(acc[ 6], d1, b23.x, acc[ 6]); FMA2(acc[ 7], d1, b23.y, acc[ 7]);
            FMA2(acc[ 8], d2, b01.x, acc[ 8]); FMA2(acc[ 9], d2, b01.y, acc[ 9]);
            FMA2(acc[10], d2, b23.x, acc[10]); FMA2(acc[11], d2, b23.y, acc[11]);
            FMA2(acc[12], d3, b01.x, acc[12]); FMA2(acc[13], d3, b01.y, acc[13]);
            FMA2(acc[14], d3, b23.x, acc[14]); FMA2(acc[15], d3, b23.y, acc[15]);
            FMA2(acc[16], d4, b01.x, acc[16]); FMA2(acc[17], d4, b01.y, acc[17]);
            FMA2(acc[18], d4, b23.x, acc[18]); FMA2(acc[19], d4, b23.y, acc[19]);
            FMA2(acc[20], d5, b01.x, acc[20]); FMA2(acc[21], d5, b01.y, acc[21]);
            FMA2(acc[22], d5, b23.x, acc[22]); FMA2(acc[23], d5, b23.y, acc[23]);
            FMA2(acc[24], d6, b01.x, acc[24]); FMA2(acc[25], d6, b01.y, acc[25]);
            FMA2(acc[26], d6, b23.x, acc[26]); FMA2(acc[27], d6, b23.y, acc[27]);
            FMA2(acc[28], d7, b01.x, acc[28]); FMA2(acc[29], d7, b01.y, acc[29]);
            FMA2(acc[30], d7, b23.x, acc[30]); FMA2(acc[31], d7, b23.y, acc[31]);
        }
    }
    __syncthreads();   // all reads of act complete (part overlaps act)

    // ===== epilogue: relu + masked per-8-row-group partials =====
    {
        float vf[8];
#pragma unroll
        for (int mi = 0; mi < 8; mi++) vf[mi] = validf[m0 + mi];
#pragma unroll
        for (int oj = 0; oj < 4; oj++){
            float slo = 0.f, shi = 0.f;
#pragma unroll
            for (int mi = 0; mi < 8; mi++){
                float lo, hi;
                UNPACK2(lo, hi, acc[mi*4 + oj]);
                slo += fmaxf(lo, 0.f)*vf[mi];
                shi += fmaxf(hi, 0.f)*vf[mi];
            }
            part[mt*64 + o0 + 2*oj    ] = slo;
            part[mt*64 + o0 + 2*oj + 1] = shi;
        }
    }
    __syncthreads();

    // ===== final: 2-group sum + mean + shortcut + relu =====
#pragma unroll
    for (int s = 0; s < 4; s++){
        const int idx = tid + s*128;        // 512 outputs: 8 points x 64 ch
        const int o   = idx >> 3;
        const int pl  = idx & 7;
        const int pt  = pt0 + pl;
        const int p   = pt & (NP-1);
        float sum = part[(pl*2+0)*64 + o] + part[(pl*2+1)*64 + o];
        float denom = fmaxf(vcnt[pl], 1e-8f);
        float res = fmaxf(sum/denom + g_SC[(size_t)pt*64 + o], 0.f);
        out[((size_t)n*64 + o)*NP + p] = res;
    }
}

// ---------------- launch ----------------
extern "C" void kernel_launch(void* const* d_in, const int* in_sizes, int n_in,
                              void* d_out, int out_size)
{
    const float* feats = (const float*)d_in[0];
    const unsigned char* mask = (const unsigned char*)d_in[1];
    const float* W0 = (const float*)d_in[2];
    const float* W1 = (const float*)d_in[3];
    const float* W2 = (const float*)d_in[4];
    const float* Ws = (const float*)d_in[5];

    cudaFuncSetAttribute(edge_kernel, cudaFuncAttributeMaxDynamicSharedMemorySize, SM_TOTAL);

    fold_kernel<<<16, 256>>>(W0, W1, W2, Ws,
        (const float*)d_in[6],  (const float*)d_in[7],  (const float*)d_in[8],  (const float*)d_in[9],
        (const float*)d_in[10], (const float*)d_in[11], (const float*)d_in[12], (const float*)d_in[13],
        (const float*)d_in[14], (const float*)d_in[15], (const float*)d_in[16], (const float*)d_in[17],
        (const float*)d_in[18], (const float*)d_in[19], (const float*)d_in[20], (const float*)d_in[21]);

    pack_kernel<<<NB, 256>>>(feats, mask);
    knn_kernel<<<NB*128, 256>>>(feats, mask);
    edge_kernel<<<NB*NP/8, 128, SM_TOTAL>>>((float*)d_out);
}